// round 13
// baseline (speedup 1.0000x reference)
#include <cuda.h>
#include <cuda_runtime.h>
#include <cstdint>

// Equivariant linear: segments (u,i) = (64,1),(32,3),(16,5); in==out dim 240.
// R10 kernel with 32-row tiles -> smem 52.2KB -> 3 CTAs/SM (occupancy lever).
// Same per-row wavefront geometry; half the accumulators per lane.

typedef unsigned long long u64;

__device__ __forceinline__ u64 fma2(u64 a, u64 b, u64 c) {
    u64 d;
    asm("fma.rn.f32x2 %0, %1, %2, %3;" : "=l"(d) : "l"(a), "l"(b), "l"(c));
    return d;
}
__device__ __forceinline__ u64 dup2(float x) {
    u64 d;
    asm("mov.b64 %0, {%1, %2};" : "=l"(d) : "f"(x), "f"(x));
    return d;
}
__device__ __forceinline__ void unpack2(u64 v, float& a, float& b) {
    asm("mov.b64 {%0, %1}, %2;" : "=f"(a), "=f"(b) : "l"(v));
}
__device__ __forceinline__ uint32_t s2u(const void* p) {
    uint32_t a;
    asm("{ .reg .u64 t; cvta.to.shared.u64 t, %1; cvt.u32.u64 %0, t; }"
        : "=r"(a) : "l"(p));
    return a;
}
__device__ __forceinline__ void mbar_wait0(uint32_t mbar) {
    asm volatile(
        "{\n\t.reg .pred P;\n\t"
        "W%=:\n\t"
        "mbarrier.try_wait.parity.shared.b64 P, [%0], 0;\n\t"
        "@P bra.uni D%=;\n\t"
        "bra.uni W%=;\n\t"
        "D%=:\n\t}"
        :: "r"(mbar) : "memory");
}
__device__ __forceinline__ void tma_load2d(uint32_t dst, const CUtensorMap* m,
                                           int cx, int cy, uint32_t mbar) {
    asm volatile(
        "cp.async.bulk.tensor.2d.shared::cta.global.tile.mbarrier::complete_tx::bytes "
        "[%0], [%1, {%2, %3}], [%4];"
        :: "r"(dst), "l"(m), "r"(cx), "r"(cy), "r"(mbar) : "memory");
}
__device__ __forceinline__ void tma_store2d(const CUtensorMap* m, int cx, int cy,
                                            uint32_t src) {
    asm volatile(
        "cp.async.bulk.tensor.2d.global.shared::cta.tile.bulk_group "
        "[%0, {%1, %2}], [%3];"
        :: "l"(m), "r"(cx), "r"(cy), "r"(src) : "memory");
}

#define T0W 100
#define T1W 140
#define TROWS 32
#define SX0_OFF 5376
#define SX1_OFF (SX0_OFF + TROWS * T0W)      // 8576
#define MBAR_OFF (SX1_OFF + TROWS * T1W)     // 13056
#define SMEM_BYTES ((MBAR_OFF + 4) * 4)      // 52240

__global__ __launch_bounds__(256, 3) void eqlin_kernel(
    const __grid_constant__ CUtensorMap mi0,
    const __grid_constant__ CUtensorMap mi1,
    const __grid_constant__ CUtensorMap mo0,
    const __grid_constant__ CUtensorMap mo1,
    const float* __restrict__ w)
{
    extern __shared__ __align__(128) float sm[];
    float* sw  = sm;
    float* sx0 = sm + SX0_OFF;
    float* sx1 = sm + SX1_OFF;
    const uint32_t mbar = s2u(sm + MBAR_OFF);

    const int tid = threadIdx.x;
    const int row0 = blockIdx.x * TROWS;

    if (tid == 0)
        asm volatile("mbarrier.init.shared.b64 [%0], 1;" :: "r"(mbar) : "memory");
    __syncthreads();
    if (tid == 0) {
        asm volatile("mbarrier.arrive.expect_tx.shared.b64 _, [%0], 30720;"
                     :: "r"(mbar) : "memory");
        tma_load2d(s2u(sx0), &mi0, 0,   row0, mbar);
        tma_load2d(s2u(sx1), &mi1, 100, row0, mbar);
    }

    // ---- stage weights (overlaps TMA), pre-scaled, plain layout ----
    #pragma unroll
    for (int k = 0; k < 21; k++) {
        int idx = tid + k * 256;
        float s = (idx < 4096) ? 0.125f
                 : (idx < 5120) ? 0.17677669529663687f
                                : 0.25f;
        sw[idx] = w[idx] * s;
    }
    __syncthreads();
    mbar_wait0(mbar);

    const int warp = tid >> 5, lane = tid & 31;

    // ================= Segment 1: warp tile 8r x 32v ======================
    // warp: rg = warp>>1 (rows 8rg..8rg+7), vh = warp&1 (v half)
    // lane: lv = lane&7 (v0 = 32vh+4lv), lr = lane>>3; rows 8rg+lr, 8rg+lr+4
    {
        const int rg = warp >> 1, vh = warp & 1;
        const int lv = lane & 7, lr = lane >> 3;
        const int v0 = 32 * vh + 4 * lv;
        const ulonglong2* w1p = (const ulonglong2*)sw;
        const float* xb = sx0 + (8 * rg + lr) * T0W;

        u64 aA0 = 0, aB0 = 0, aA1 = 0, aB1 = 0;

        #pragma unroll 4
        for (int k4 = 0; k4 < 16; k4++) {
            float4 x0 = *(const float4*)(xb + 4 * k4);
            float4 x1 = *(const float4*)(xb + 4 * T0W + 4 * k4);
            #pragma unroll
            for (int uu = 0; uu < 4; uu++) {
                ulonglong2 wp = w1p[(4 * k4 + uu) * 16 + 8 * vh + lv];
                float e0 = (uu == 0) ? x0.x : (uu == 1) ? x0.y : (uu == 2) ? x0.z : x0.w;
                float e1 = (uu == 0) ? x1.x : (uu == 1) ? x1.y : (uu == 2) ? x1.z : x1.w;
                u64 d0 = dup2(e0), d1 = dup2(e1);
                aA0 = fma2(d0, wp.x, aA0);  aB0 = fma2(d0, wp.y, aB0);
                aA1 = fma2(d1, wp.x, aA1);  aB1 = fma2(d1, wp.y, aB1);
            }
        }
        __syncthreads();   // all seg1 reads (cols 0-63) done everywhere
        float* pb = sx0 + (8 * rg + lr) * T0W + v0;
        {
            float4 o; unpack2(aA0, o.x, o.y); unpack2(aB0, o.z, o.w);
            *(float4*)(pb) = o;
        }
        {
            float4 o; unpack2(aA1, o.x, o.y); unpack2(aB1, o.z, o.w);
            *(float4*)(pb + 4 * T0W) = o;
        }
    }

    // ================= Segment 2: 2 rows/thread, v-pair ====================
    // ty = tid>>4 (rows ty, ty+16), tx = tid&15 (v-pair 2tx)
    {
        const int ty = tid >> 4, tx = tid & 15;
        const u64* w2p = (const u64*)(sw + 4096);
        u64 a20 = 0, a21 = 0, a22 = 0;      // row ty
        u64 b20 = 0, b21 = 0, b22 = 0;      // row ty+16

        #pragma unroll
        for (int k4 = 0; k4 < 8; k4++) {    // k4 0-2: sx0 (cols 64-99); 3-7: sx1
            u64 wp0 = w2p[(4 * k4 + 0) * 16 + tx];
            u64 wp1 = w2p[(4 * k4 + 1) * 16 + tx];
            u64 wp2 = w2p[(4 * k4 + 2) * 16 + tx];
            u64 wp3 = w2p[(4 * k4 + 3) * 16 + tx];
            const float* ba = (k4 < 3) ? (sx0 + ty * T0W + 64 + 12 * k4)
                                       : (sx1 + ty * T1W + 12 * k4 - 36);
            const float* bb = (k4 < 3) ? (sx0 + (ty + 16) * T0W + 64 + 12 * k4)
                                       : (sx1 + (ty + 16) * T1W + 12 * k4 - 36);
            float4 qa0 = *(const float4*)(ba);
            float4 qa1 = *(const float4*)(ba + 4);
            float4 qa2 = *(const float4*)(ba + 8);
            float4 qb0 = *(const float4*)(bb);
            float4 qb1 = *(const float4*)(bb + 4);
            float4 qb2 = *(const float4*)(bb + 8);
            a20 = fma2(dup2(qa0.x), wp0, a20);  b20 = fma2(dup2(qb0.x), wp0, b20);
            a21 = fma2(dup2(qa0.y), wp0, a21);  b21 = fma2(dup2(qb0.y), wp0, b21);
            a22 = fma2(dup2(qa0.z), wp0, a22);  b22 = fma2(dup2(qb0.z), wp0, b22);
            a20 = fma2(dup2(qa0.w), wp1, a20);  b20 = fma2(dup2(qb0.w), wp1, b20);
            a21 = fma2(dup2(qa1.x), wp1, a21);  b21 = fma2(dup2(qb1.x), wp1, b21);
            a22 = fma2(dup2(qa1.y), wp1, a22);  b22 = fma2(dup2(qb1.y), wp1, b22);
            a20 = fma2(dup2(qa1.z), wp2, a20);  b20 = fma2(dup2(qb1.z), wp2, b20);
            a21 = fma2(dup2(qa1.w), wp2, a21);  b21 = fma2(dup2(qb1.w), wp2, b21);
            a22 = fma2(dup2(qa2.x), wp2, a22);  b22 = fma2(dup2(qb2.x), wp2, b22);
            a20 = fma2(dup2(qa2.y), wp3, a20);  b20 = fma2(dup2(qb2.y), wp3, b20);
            a21 = fma2(dup2(qa2.z), wp3, a21);  b21 = fma2(dup2(qb2.z), wp3, b21);
            a22 = fma2(dup2(qa2.w), wp3, a22);  b22 = fma2(dup2(qb2.w), wp3, b22);
        }
        __syncthreads();   // all seg2 reads (cols 64-159) done everywhere
        {
            float* p = (tx < 6) ? (sx0 + ty * T0W + 64 + 6 * tx)
                                : (sx1 + ty * T1W + 6 * tx - 36);
            float l0, h0, l1, h1, l2, h2;
            unpack2(a20, l0, h0); unpack2(a21, l1, h1); unpack2(a22, l2, h2);
            *(float2*)(p)     = make_float2(l0, l1);
            *(float2*)(p + 2) = make_float2(l2, h0);
            *(float2*)(p + 4) = make_float2(h1, h2);
        }
        {
            float* p = (tx < 6) ? (sx0 + (ty + 16) * T0W + 64 + 6 * tx)
                                : (sx1 + (ty + 16) * T1W + 6 * tx - 36);
            float l0, h0, l1, h1, l2, h2;
            unpack2(b20, l0, h0); unpack2(b21, l1, h1); unpack2(b22, l2, h2);
            *(float2*)(p)     = make_float2(l0, l1);
            *(float2*)(p + 2) = make_float2(l2, h0);
            *(float2*)(p + 4) = make_float2(h1, h2);
        }
    }

    // ================= Segment 3: warp tile 4r x 16v, v-pairs ===============
    // lane: lv3 = lane&7 (v-pair 2lv3), lr3 = lane>>3; row = 4warp + lr3
    {
        const int lv3 = lane & 7, lr3 = lane >> 3;
        const int row = 4 * warp + lr3;
        const u64* w3q = (const u64*)(sw + 5120);  // pair idx u*8+lv3
        u64 c0 = 0, c1 = 0, c2 = 0, c3 = 0, c4 = 0;

        #pragma unroll
        for (int k4 = 0; k4 < 4; k4++) {
            const float* pa = sx1 + row * T1W + 60 + 20 * k4;
            float4 q0 = *(const float4*)(pa);
            float4 q1 = *(const float4*)(pa + 4);
            float4 q2 = *(const float4*)(pa + 8);
            float4 q3 = *(const float4*)(pa + 12);
            float4 q4 = *(const float4*)(pa + 16);
            u64 wu0 = w3q[(4 * k4 + 0) * 8 + lv3];
            u64 wu1 = w3q[(4 * k4 + 1) * 8 + lv3];
            u64 wu2 = w3q[(4 * k4 + 2) * 8 + lv3];
            u64 wu3 = w3q[(4 * k4 + 3) * 8 + lv3];
            c0 = fma2(dup2(q0.x), wu0, c0);
            c1 = fma2(dup2(q0.y), wu0, c1);
            c2 = fma2(dup2(q0.z), wu0, c2);
            c3 = fma2(dup2(q0.w), wu0, c3);
            c4 = fma2(dup2(q1.x), wu0, c4);
            c0 = fma2(dup2(q1.y), wu1, c0);
            c1 = fma2(dup2(q1.z), wu1, c1);
            c2 = fma2(dup2(q1.w), wu1, c2);
            c3 = fma2(dup2(q2.x), wu1, c3);
            c4 = fma2(dup2(q2.y), wu1, c4);
            c0 = fma2(dup2(q2.z), wu2, c0);
            c1 = fma2(dup2(q2.w), wu2, c1);
            c2 = fma2(dup2(q3.x), wu2, c2);
            c3 = fma2(dup2(q3.y), wu2, c3);
            c4 = fma2(dup2(q3.z), wu2, c4);
            c0 = fma2(dup2(q3.w), wu3, c0);
            c1 = fma2(dup2(q4.x), wu3, c1);
            c2 = fma2(dup2(q4.y), wu3, c2);
            c3 = fma2(dup2(q4.z), wu3, c3);
            c4 = fma2(dup2(q4.w), wu3, c4);
        }
        __syncthreads();   // all seg3 reads done everywhere
        float* pA = sx1 + row * T1W + 60 + 10 * lv3;
        float l0, h0, l1, h1, l2, h2, l3, h3, l4, h4;
        unpack2(c0, l0, h0); unpack2(c1, l1, h1); unpack2(c2, l2, h2);
        unpack2(c3, l3, h3); unpack2(c4, l4, h4);
        *(float2*)(pA)     = make_float2(l0, l1);
        *(float2*)(pA + 2) = make_float2(l2, l3);
        *(float2*)(pA + 4) = make_float2(l4, h0);
        *(float2*)(pA + 6) = make_float2(h1, h2);
        *(float2*)(pA + 8) = make_float2(h3, h4);
    }

    __syncthreads();
    if (tid == 0) {
        asm volatile("fence.proxy.async;" ::: "memory");
        tma_store2d(&mo0, 0,   row0, s2u(sx0));
        tma_store2d(&mo1, 100, row0, s2u(sx1));
        asm volatile("cp.async.bulk.commit_group;" ::: "memory");
        asm volatile("cp.async.bulk.wait_group 0;" ::: "memory");
    }
}

// ===================== host side =====================

typedef CUresult (*TmapEncodeFn)(
    CUtensorMap*, CUtensorMapDataType, cuuint32_t, void*,
    const cuuint64_t*, const cuuint64_t*, const cuuint32_t*, const cuuint32_t*,
    CUtensorMapInterleave, CUtensorMapSwizzle, CUtensorMapL2promotion,
    CUtensorMapFloatOOBfill);

static void enc_map(TmapEncodeFn f, CUtensorMap* m, void* base, long long n,
                    uint32_t boxw) {
    cuuint64_t dims[2]    = {240, (cuuint64_t)n};
    cuuint64_t strides[1] = {240 * 4};
    cuuint32_t box[2]     = {boxw, TROWS};
    cuuint32_t es[2]      = {1, 1};
    f(m, CU_TENSOR_MAP_DATA_TYPE_FLOAT32, 2, base, dims, strides, box, es,
      CU_TENSOR_MAP_INTERLEAVE_NONE, CU_TENSOR_MAP_SWIZZLE_NONE,
      CU_TENSOR_MAP_L2_PROMOTION_L2_128B, CU_TENSOR_MAP_FLOAT_OOB_FILL_NONE);
}

extern "C" void kernel_launch(void* const* d_in, const int* in_sizes, int n_in,
                              void* d_out, int out_size) {
    void* x = d_in[0];
    const float* w = (const float*)d_in[1];
    const long long n = in_sizes[0] / 240;          // 200000
    const int blocks = (int)((n + TROWS - 1) / TROWS);   // 6250

    void* fp = nullptr;
    cudaDriverEntryPointQueryResult qr;
#if CUDART_VERSION >= 12050
    cudaGetDriverEntryPointByVersion("cuTensorMapEncodeTiled", &fp, 12000,
                                     cudaEnableDefault, &qr);
#else
    cudaGetDriverEntryPoint("cuTensorMapEncodeTiled", &fp, cudaEnableDefault, &qr);
#endif
    TmapEncodeFn enc = (TmapEncodeFn)fp;

    CUtensorMap mi0, mi1, mo0, mo1;
    enc_map(enc, &mi0, x, n, 100);
    enc_map(enc, &mi1, x, n, 140);
    enc_map(enc, &mo0, d_out, n, 100);
    enc_map(enc, &mo1, d_out, n, 140);

    static bool attr_set = false;
    if (!attr_set) {
        cudaFuncSetAttribute(eqlin_kernel,
                             cudaFuncAttributeMaxDynamicSharedMemorySize, SMEM_BYTES);
        attr_set = true;
    }
    eqlin_kernel<<<blocks, 256, SMEM_BYTES>>>(mi0, mi1, mo0, mo1, w);
}

// round 15
// speedup vs baseline: 1.2312x; 1.2312x over previous
#include <cuda.h>
#include <cuda_runtime.h>
#include <cstdint>

// Equivariant linear: segments (u,i) = (64,1),(32,3),(16,5); in==out dim 240.
// R10 orchestration. Seg1 = K-pair fma2 with chunked u-pair-major weights:
// each warp w-load reads one contiguous 128B region (1 wavefront) and both
// fma2 operands come straight from memory (zero dup movs in seg1).

typedef unsigned long long u64;

__device__ __forceinline__ u64 fma2(u64 a, u64 b, u64 c) {
    u64 d;
    asm("fma.rn.f32x2 %0, %1, %2, %3;" : "=l"(d) : "l"(a), "l"(b), "l"(c));
    return d;
}
__device__ __forceinline__ u64 dup2(float x) {
    u64 d;
    asm("mov.b64 %0, {%1, %2};" : "=l"(d) : "f"(x), "f"(x));
    return d;
}
__device__ __forceinline__ float hsum2(u64 v) {
    float a, b;
    asm("mov.b64 {%0, %1}, %2;" : "=f"(a), "=f"(b) : "l"(v));
    return a + b;
}
__device__ __forceinline__ void unpack2(u64 v, float& a, float& b) {
    asm("mov.b64 {%0, %1}, %2;" : "=f"(a), "=f"(b) : "l"(v));
}
__device__ __forceinline__ uint32_t s2u(const void* p) {
    uint32_t a;
    asm("{ .reg .u64 t; cvta.to.shared.u64 t, %1; cvt.u32.u64 %0, t; }"
        : "=r"(a) : "l"(p));
    return a;
}
__device__ __forceinline__ void mbar_wait0(uint32_t mbar) {
    asm volatile(
        "{\n\t.reg .pred P;\n\t"
        "W%=:\n\t"
        "mbarrier.try_wait.parity.shared.b64 P, [%0], 0;\n\t"
        "@P bra.uni D%=;\n\t"
        "bra.uni W%=;\n\t"
        "D%=:\n\t}"
        :: "r"(mbar) : "memory");
}
__device__ __forceinline__ void tma_load2d(uint32_t dst, const CUtensorMap* m,
                                           int cx, int cy, uint32_t mbar) {
    asm volatile(
        "cp.async.bulk.tensor.2d.shared::cta.global.tile.mbarrier::complete_tx::bytes "
        "[%0], [%1, {%2, %3}], [%4];"
        :: "r"(dst), "l"(m), "r"(cx), "r"(cy), "r"(mbar) : "memory");
}
__device__ __forceinline__ void tma_store2d(const CUtensorMap* m, int cx, int cy,
                                            uint32_t src) {
    asm volatile(
        "cp.async.bulk.tensor.2d.global.shared::cta.tile.bulk_group "
        "[%0, {%1, %2}], [%3];"
        :: "l"(m), "r"(cx), "r"(cy), "r"(src) : "memory");
}

#define T0W 100
#define T1W 140
#define SX0_OFF 5376
#define SX1_OFF (SX0_OFF + 64 * T0W)      // 11776
#define MBAR_OFF (SX1_OFF + 64 * T1W)     // 20736
#define SMEM_BYTES ((MBAR_OFF + 4) * 4)   // 82960

__global__ __launch_bounds__(256, 2) void eqlin_kernel(
    const __grid_constant__ CUtensorMap mi0,
    const __grid_constant__ CUtensorMap mi1,
    const __grid_constant__ CUtensorMap mo0,
    const __grid_constant__ CUtensorMap mo1,
    const float* __restrict__ w)
{
    extern __shared__ __align__(128) float sm[];
    float* sw  = sm;
    float* sx0 = sm + SX0_OFF;
    float* sx1 = sm + SX1_OFF;
    const uint32_t mbar = s2u(sm + MBAR_OFF);

    const int tid = threadIdx.x;
    const int row0 = blockIdx.x * 64;

    if (tid == 0)
        asm volatile("mbarrier.init.shared.b64 [%0], 1;" :: "r"(mbar) : "memory");
    __syncthreads();
    if (tid == 0) {
        asm volatile("mbarrier.arrive.expect_tx.shared.b64 _, [%0], 61440;"
                     :: "r"(mbar) : "memory");
        tma_load2d(s2u(sx0), &mi0, 0,   row0, mbar);
        tma_load2d(s2u(sx1), &mi1, 100, row0, mbar);
    }

    // ---- stage weights (overlaps TMA) ----
    // seg1 chunked u-pair-major: float dst index =
    //   k4*256 + vh*128 + c*32 + lv*4 + e
    // with u = 4k4+uu, v = 32vh + 8? no: v = 32vh+4lv+ve (lv 0..7, ve 0..3),
    //   c = (uu>>1)*2 + (ve>>1),  e = ((ve&1)<<1) | (uu&1).
    // Each (k4,vh,c) 128B block holds, at lane offset lv*16B, the ulonglong2:
    //   ( pair(u-base, v0+2*(c&1)), pair(u-base, v0+2*(c&1)+1) ), u-base = 4k4+2*(c>>1).
    #pragma unroll
    for (int k = 0; k < 16; k++) {
        int idx = tid + k * 256;                 // = u*64 + v
        int u = idx >> 6, v = idx & 63;
        int k4 = u >> 2, uu = u & 3;
        int vh = v >> 5, lv = (v >> 2) & 7, ve = v & 3;
        int c = ((uu >> 1) << 1) | (ve >> 1);
        int e = ((ve & 1) << 1) | (uu & 1);
        sw[k4 * 256 + vh * 128 + c * 32 + lv * 4 + e] = w[idx] * 0.125f;
    }
    #pragma unroll
    for (int k = 0; k < 5; k++) {                // seg2/seg3 plain scaled copy
        int idx = 4096 + tid + k * 256;
        float s = (idx < 5120) ? 0.17677669529663687f : 0.25f;
        sw[idx] = w[idx] * s;
    }
    __syncthreads();
    mbar_wait0(mbar);

    const int warp = tid >> 5, lane = tid & 31;

    // ================= Segment 1: 16r x 32v per warp, K-pair ================
    // warp: rg = warp>>1 (rows 16rg..), vh = warp&1 (v half)
    // lane: lv = lane&7 (v0 = 32vh+4lv), lr = lane>>3; rows 16rg+lr+4rr
    {
        const int rg = warp >> 1, vh = warp & 1;
        const int lv = lane & 7, lr = lane >> 3;
        const float* xb = sx0 + (16 * rg + lr) * T0W;
        const float* wl = sw + vh * 128 + lv * 4;

        u64 a00 = 0, a01 = 0, a02 = 0, a03 = 0;   // row lr+0,  v0..v0+3
        u64 a10 = 0, a11 = 0, a12 = 0, a13 = 0;   // row lr+4
        u64 a20 = 0, a21 = 0, a22 = 0, a23 = 0;   // row lr+8
        u64 a30 = 0, a31 = 0, a32 = 0, a33 = 0;   // row lr+12

        #pragma unroll 2
        for (int k4 = 0; k4 < 16; k4++) {
            const float* wb = wl + k4 * 256;
            // W0/W0b: u-pair (4k4,4k4+1) for (v0,v0+1)/(v0+2,v0+3)
            // W1/W1b: u-pair (4k4+2,4k4+3)
            ulonglong2 W0  = *(const ulonglong2*)(wb);
            ulonglong2 W0b = *(const ulonglong2*)(wb + 32);
            ulonglong2 W1  = *(const ulonglong2*)(wb + 64);
            ulonglong2 W1b = *(const ulonglong2*)(wb + 96);
            ulonglong2 x0 = *(const ulonglong2*)(xb + 4 * k4);
            ulonglong2 x1 = *(const ulonglong2*)(xb + 4 * T0W + 4 * k4);
            ulonglong2 x2 = *(const ulonglong2*)(xb + 8 * T0W + 4 * k4);
            ulonglong2 x3 = *(const ulonglong2*)(xb + 12 * T0W + 4 * k4);
            a00 = fma2(x0.y, W1.x,  fma2(x0.x, W0.x,  a00));
            a01 = fma2(x0.y, W1.y,  fma2(x0.x, W0.y,  a01));
            a02 = fma2(x0.y, W1b.x, fma2(x0.x, W0b.x, a02));
            a03 = fma2(x0.y, W1b.y, fma2(x0.x, W0b.y, a03));
            a10 = fma2(x1.y, W1.x,  fma2(x1.x, W0.x,  a10));
            a11 = fma2(x1.y, W1.y,  fma2(x1.x, W0.y,  a11));
            a12 = fma2(x1.y, W1b.x, fma2(x1.x, W0b.x, a12));
            a13 = fma2(x1.y, W1b.y, fma2(x1.x, W0b.y, a13));
            a20 = fma2(x2.y, W1.x,  fma2(x2.x, W0.x,  a20));
            a21 = fma2(x2.y, W1.y,  fma2(x2.x, W0.y,  a21));
            a22 = fma2(x2.y, W1b.x, fma2(x2.x, W0b.x, a22));
            a23 = fma2(x2.y, W1b.y, fma2(x2.x, W0b.y, a23));
            a30 = fma2(x3.y, W1.x,  fma2(x3.x, W0.x,  a30));
            a31 = fma2(x3.y, W1.y,  fma2(x3.x, W0.y,  a31));
            a32 = fma2(x3.y, W1b.x, fma2(x3.x, W0b.x, a32));
            a33 = fma2(x3.y, W1b.y, fma2(x3.x, W0b.y, a33));
        }
        __syncthreads();   // all seg1 reads (cols 0-63) done everywhere
        float* pb = sx0 + (16 * rg + lr) * T0W + 32 * vh + 4 * lv;
        *(float4*)(pb) =
            make_float4(hsum2(a00), hsum2(a01), hsum2(a02), hsum2(a03));
        *(float4*)(pb + 4 * T0W) =
            make_float4(hsum2(a10), hsum2(a11), hsum2(a12), hsum2(a13));
        *(float4*)(pb + 8 * T0W) =
            make_float4(hsum2(a20), hsum2(a21), hsum2(a22), hsum2(a23));
        *(float4*)(pb + 12 * T0W) =
            make_float4(hsum2(a30), hsum2(a31), hsum2(a32), hsum2(a33));
    }

    // ================= Segment 2: R10 shape (unchanged) =====================
    {
        const int ty = tid >> 4, tx = tid & 15;
        const u64* w2p = (const u64*)(sw + 4096);
        u64 a2[4][3];
        #pragma unroll
        for (int s = 0; s < 4; s++)
            #pragma unroll
            for (int i = 0; i < 3; i++) a2[s][i] = 0ull;

        #pragma unroll
        for (int k4 = 0; k4 < 8; k4++) {        // k4 0-2: sx0 (cols 64-99); 3-7: sx1
            u64 wp0 = w2p[(4 * k4 + 0) * 16 + tx];
            u64 wp1 = w2p[(4 * k4 + 1) * 16 + tx];
            u64 wp2 = w2p[(4 * k4 + 2) * 16 + tx];
            u64 wp3 = w2p[(4 * k4 + 3) * 16 + tx];
            #pragma unroll
            for (int s = 0; s < 4; s++) {
                const int row = ty + 16 * s;
                const float* b = (k4 < 3) ? (sx0 + row * T0W + 64 + 12 * k4)
                                          : (sx1 + row * T1W + 12 * k4 - 36);
                float4 xb0 = *(const float4*)(b);
                float4 xb1 = *(const float4*)(b + 4);
                float4 xb2 = *(const float4*)(b + 8);
                a2[s][0] = fma2(dup2(xb0.x), wp0, a2[s][0]);
                a2[s][1] = fma2(dup2(xb0.y), wp0, a2[s][1]);
                a2[s][2] = fma2(dup2(xb0.z), wp0, a2[s][2]);
                a2[s][0] = fma2(dup2(xb0.w), wp1, a2[s][0]);
                a2[s][1] = fma2(dup2(xb1.x), wp1, a2[s][1]);
                a2[s][2] = fma2(dup2(xb1.y), wp1, a2[s][2]);
                a2[s][0] = fma2(dup2(xb1.z), wp2, a2[s][0]);
                a2[s][1] = fma2(dup2(xb1.w), wp2, a2[s][1]);
                a2[s][2] = fma2(dup2(xb2.x), wp2, a2[s][2]);
                a2[s][0] = fma2(dup2(xb2.y), wp3, a2[s][0]);
                a2[s][1] = fma2(dup2(xb2.z), wp3, a2[s][1]);
                a2[s][2] = fma2(dup2(xb2.w), wp3, a2[s][2]);
            }
        }
        __syncthreads();   // all seg2 reads (cols 64-159) done everywhere
        #pragma unroll
        for (int s = 0; s < 4; s++) {
            const int row = ty + 16 * s;
            float* p = (tx < 6) ? (sx0 + row * T0W + 64 + 6 * tx)
                                : (sx1 + row * T1W + 6 * tx - 36);
            float l0, h0, l1, h1, l2, h2;
            unpack2(a2[s][0], l0, h0);
            unpack2(a2[s][1], l1, h1);
            unpack2(a2[s][2], l2, h2);
            *(float2*)(p)     = make_float2(l0, l1);
            *(float2*)(p + 2) = make_float2(l2, h0);
            *(float2*)(p + 4) = make_float2(h1, h2);
        }
    }

    // ================= Segment 3: R10 shape (unchanged) =====================
    {
        const int lv3 = lane & 7, lr3 = lane >> 3;
        const int rbase = 8 * warp + lr3;          // rows rbase, rbase+4
        const u64* w3q = (const u64*)(sw + 5120);  // pair idx u*8+lv3
        u64 cA0 = 0, cA1 = 0, cA2 = 0, cA3 = 0, cA4 = 0;
        u64 cB0 = 0, cB1 = 0, cB2 = 0, cB3 = 0, cB4 = 0;

        #pragma unroll
        for (int k4 = 0; k4 < 4; k4++) {
            const float* pa = sx1 + rbase * T1W + 60 + 20 * k4;
            const float* pb = pa + 4 * T1W;
            float4 qa0 = *(const float4*)(pa);
            float4 qa1 = *(const float4*)(pa + 4);
            float4 qa2 = *(const float4*)(pa + 8);
            float4 qa3 = *(const float4*)(pa + 12);
            float4 qa4 = *(const float4*)(pa + 16);
            float4 qb0 = *(const float4*)(pb);
            float4 qb1 = *(const float4*)(pb + 4);
            float4 qb2 = *(const float4*)(pb + 8);
            float4 qb3 = *(const float4*)(pb + 12);
            float4 qb4 = *(const float4*)(pb + 16);
            u64 wu0 = w3q[(4 * k4 + 0) * 8 + lv3];
            u64 wu1 = w3q[(4 * k4 + 1) * 8 + lv3];
            u64 wu2 = w3q[(4 * k4 + 2) * 8 + lv3];
            u64 wu3 = w3q[(4 * k4 + 3) * 8 + lv3];
            cA0 = fma2(dup2(qa0.x), wu0, cA0);  cB0 = fma2(dup2(qb0.x), wu0, cB0);
            cA1 = fma2(dup2(qa0.y), wu0, cA1);  cB1 = fma2(dup2(qb0.y), wu0, cB1);
            cA2 = fma2(dup2(qa0.z), wu0, cA2);  cB2 = fma2(dup2(qb0.z), wu0, cB2);
            cA3 = fma2(dup2(qa0.w), wu0, cA3);  cB3 = fma2(dup2(qb0.w), wu0, cB3);
            cA4 = fma2(dup2(qa1.x), wu0, cA4);  cB4 = fma2(dup2(qb1.x), wu0, cB4);
            cA0 = fma2(dup2(qa1.y), wu1, cA0);  cB0 = fma2(dup2(qb1.y), wu1, cB0);
            cA1 = fma2(dup2(qa1.z), wu1, cA1);  cB1 = fma2(dup2(qb1.z), wu1, cB1);
            cA2 = fma2(dup2(qa1.w), wu1, cA2);  cB2 = fma2(dup2(qb1.w), wu1, cB2);
            cA3 = fma2(dup2(qa2.x), wu1, cA3);  cB3 = fma2(dup2(qb2.x), wu1, cB3);
            cA4 = fma2(dup2(qa2.y), wu1, cA4);  cB4 = fma2(dup2(qb2.y), wu1, cB4);
            cA0 = fma2(dup2(qa2.z), wu2, cA0);  cB0 = fma2(dup2(qb2.z), wu2, cB0);
            cA1 = fma2(dup2(qa2.w), wu2, cA1);  cB1 = fma2(dup2(qb2.w), wu2, cB1);
            cA2 = fma2(dup2(qa3.x), wu2, cA2);  cB2 = fma2(dup2(qb3.x), wu2, cB2);
            cA3 = fma2(dup2(qa3.y), wu2, cA3);  cB3 = fma2(dup2(qb3.y), wu2, cB3);
            cA4 = fma2(dup2(qa3.z), wu2, cA4);  cB4 = fma2(dup2(qb3.z), wu2, cB4);
            cA0 = fma2(dup2(qa3.w), wu3, cA0);  cB0 = fma2(dup2(qb3.w), wu3, cB0);
            cA1 = fma2(dup2(qa4.x), wu3, cA1);  cB1 = fma2(dup2(qb4.x), wu3, cB1);
            cA2 = fma2(dup2(qa4.y), wu3, cA2);  cB2 = fma2(dup2(qb4.y), wu3, cB2);
            cA3 = fma2(dup2(qa4.z), wu3, cA3);  cB3 = fma2(dup2(qb4.z), wu3, cB3);
            cA4 = fma2(dup2(qa4.w), wu3, cA4);  cB4 = fma2(dup2(qb4.w), wu3, cB4);
        }
        __syncthreads();   // all seg3 reads done everywhere
        float* pA = sx1 + rbase * T1W + 60 + 10 * lv3;
        float* pB = pA + 4 * T1W;
        float l0, h0, l1, h1, l2, h2, l3, h3, l4, h4;
        unpack2(cA0, l0, h0); unpack2(cA1, l1, h1); unpack2(cA2, l2, h2);
        unpack2(cA3, l3, h3); unpack2(cA4, l4, h4);
        *(float2*)(pA)     = make_float2(l0, l1);
        *(float2*)(pA + 2) = make_float2(l2, l3);
        *(float2*)(pA + 4) = make_float2(l4, h0);
        *(float2*)(pA + 6) = make_float2(h1, h2);
        *(float2*)(pA + 8) = make_float2(h3, h4);
        unpack2(cB0, l0, h0); unpack2(cB1, l1, h1); unpack2(cB2, l2, h2);
        unpack2(cB3, l3, h3); unpack2(cB4, l4, h4);
        *(float2*)(pB)     = make_float2(l0, l1);
        *(float2*)(pB + 2) = make_float2(l2, l3);
        *(float2*)(pB + 4) = make_float2(l4, h0);
        *(float2*)(pB + 6) = make_float2(h1, h2);
        *(float2*)(pB + 8) = make_float2(h3, h4);
    }

    __syncthreads();
    if (tid == 0) {
        asm volatile("fence.proxy.async;" ::: "memory");
        tma_store2d(&mo0, 0,   row0, s2u(sx0));
        tma_store2d(&mo1, 100, row0, s2u(sx1));
        asm volatile("cp.async.bulk.commit_group;" ::: "memory");
        asm volatile("cp.async.bulk.wait_group 0;" ::: "memory");
    }
}

// ===================== host side =====================

typedef CUresult (*TmapEncodeFn)(
    CUtensorMap*, CUtensorMapDataType, cuuint32_t, void*,
    const cuuint64_t*, const cuuint64_t*, const cuuint32_t*, const cuuint32_t*,
    CUtensorMapInterleave, CUtensorMapSwizzle, CUtensorMapL2promotion,
    CUtensorMapFloatOOBfill);

static void enc_map(TmapEncodeFn f, CUtensorMap* m, void* base, long long n,
                    uint32_t boxw) {
    cuuint64_t dims[2]    = {240, (cuuint64_t)n};
    cuuint64_t strides[1] = {240 * 4};
    cuuint32_t box[2]     = {boxw, 64};
    cuuint32_t es[2]      = {1, 1};
    f(m, CU_TENSOR_MAP_DATA_TYPE_FLOAT32, 2, base, dims, strides, box, es,
      CU_TENSOR_MAP_INTERLEAVE_NONE, CU_TENSOR_MAP_SWIZZLE_NONE,
      CU_TENSOR_MAP_L2_PROMOTION_L2_128B, CU_TENSOR_MAP_FLOAT_OOB_FILL_NONE);
}

extern "C" void kernel_launch(void* const* d_in, const int* in_sizes, int n_in,
                              void* d_out, int out_size) {
    void* x = d_in[0];
    const float* w = (const float*)d_in[1];
    const long long n = in_sizes[0] / 240;          // 200000
    const int blocks = (int)((n + 63) / 64);        // 3125 (exact)

    void* fp = nullptr;
    cudaDriverEntryPointQueryResult qr;
#if CUDART_VERSION >= 12050
    cudaGetDriverEntryPointByVersion("cuTensorMapEncodeTiled", &fp, 12000,
                                     cudaEnableDefault, &qr);
#else
    cudaGetDriverEntryPoint("cuTensorMapEncodeTiled", &fp, cudaEnableDefault, &qr);
#endif
    TmapEncodeFn enc = (TmapEncodeFn)fp;

    CUtensorMap mi0, mi1, mo0, mo1;
    enc_map(enc, &mi0, x, n, 100);
    enc_map(enc, &mi1, x, n, 140);
    enc_map(enc, &mo0, d_out, n, 100);
    enc_map(enc, &mo1, d_out, n, 140);

    static bool attr_set = false;
    if (!attr_set) {
        cudaFuncSetAttribute(eqlin_kernel,
                             cudaFuncAttributeMaxDynamicSharedMemorySize, SMEM_BYTES);
        attr_set = true;
    }
    eqlin_kernel<<<blocks, 256, SMEM_BYTES>>>(mi0, mi1, mo0, mo1, w);
}

// round 16
// speedup vs baseline: 1.2933x; 1.0505x over previous
#include <cuda.h>
#include <cuda_runtime.h>
#include <cstdint>

// Equivariant linear: segments (u,i) = (64,1),(32,3),(16,5); in==out dim 240.
// R10 champion body at 96-row tiles / 384 threads: +50% warps per SM at
// identical per-row cost (occupancy/latency experiment). TMA clips OOB rows.

typedef unsigned long long u64;

__device__ __forceinline__ u64 fma2(u64 a, u64 b, u64 c) {
    u64 d;
    asm("fma.rn.f32x2 %0, %1, %2, %3;" : "=l"(d) : "l"(a), "l"(b), "l"(c));
    return d;
}
__device__ __forceinline__ u64 dup2(float x) {
    u64 d;
    asm("mov.b64 %0, {%1, %2};" : "=l"(d) : "f"(x), "f"(x));
    return d;
}
__device__ __forceinline__ void unpack2(u64 v, float& a, float& b) {
    asm("mov.b64 {%0, %1}, %2;" : "=f"(a), "=f"(b) : "l"(v));
}
__device__ __forceinline__ uint32_t s2u(const void* p) {
    uint32_t a;
    asm("{ .reg .u64 t; cvta.to.shared.u64 t, %1; cvt.u32.u64 %0, t; }"
        : "=r"(a) : "l"(p));
    return a;
}
__device__ __forceinline__ void mbar_wait0(uint32_t mbar) {
    asm volatile(
        "{\n\t.reg .pred P;\n\t"
        "W%=:\n\t"
        "mbarrier.try_wait.parity.shared.b64 P, [%0], 0;\n\t"
        "@P bra.uni D%=;\n\t"
        "bra.uni W%=;\n\t"
        "D%=:\n\t}"
        :: "r"(mbar) : "memory");
}
__device__ __forceinline__ void tma_load2d(uint32_t dst, const CUtensorMap* m,
                                           int cx, int cy, uint32_t mbar) {
    asm volatile(
        "cp.async.bulk.tensor.2d.shared::cta.global.tile.mbarrier::complete_tx::bytes "
        "[%0], [%1, {%2, %3}], [%4];"
        :: "r"(dst), "l"(m), "r"(cx), "r"(cy), "r"(mbar) : "memory");
}
__device__ __forceinline__ void tma_store2d(const CUtensorMap* m, int cx, int cy,
                                            uint32_t src) {
    asm volatile(
        "cp.async.bulk.tensor.2d.global.shared::cta.tile.bulk_group "
        "[%0, {%1, %2}], [%3];"
        :: "l"(m), "r"(cx), "r"(cy), "r"(src) : "memory");
}

#define T0W 100
#define T1W 140
#define TROWS 96
#define NTHR 384
#define SX0_OFF 5376
#define SX1_OFF (SX0_OFF + TROWS * T0W)      // 14976
#define MBAR_OFF (SX1_OFF + TROWS * T1W)     // 28416
#define SMEM_BYTES ((MBAR_OFF + 4) * 4)      // 113680

__global__ __launch_bounds__(NTHR, 2) void eqlin_kernel(
    const __grid_constant__ CUtensorMap mi0,
    const __grid_constant__ CUtensorMap mi1,
    const __grid_constant__ CUtensorMap mo0,
    const __grid_constant__ CUtensorMap mo1,
    const float* __restrict__ w)
{
    extern __shared__ __align__(128) float sm[];
    float* sw  = sm;
    float* sx0 = sm + SX0_OFF;
    float* sx1 = sm + SX1_OFF;
    const uint32_t mbar = s2u(sm + MBAR_OFF);

    const int tid = threadIdx.x;
    const int row0 = blockIdx.x * TROWS;

    if (tid == 0)
        asm volatile("mbarrier.init.shared.b64 [%0], 1;" :: "r"(mbar) : "memory");
    __syncthreads();
    if (tid == 0) {
        // OOB rows zero-fill on load, clip on store: no predicates needed.
        asm volatile("mbarrier.arrive.expect_tx.shared.b64 _, [%0], 92160;"
                     :: "r"(mbar) : "memory");
        tma_load2d(s2u(sx0), &mi0, 0,   row0, mbar);
        tma_load2d(s2u(sx1), &mi1, 100, row0, mbar);
    }

    // ---- stage weights (overlaps TMA), pre-scaled, plain layout ----
    #pragma unroll
    for (int k = 0; k < 14; k++) {               // 14*384 = 5376 exactly
        int idx = tid + k * NTHR;
        float s = (idx < 4096) ? 0.125f
                 : (idx < 5120) ? 0.17677669529663687f
                                : 0.25f;
        sw[idx] = w[idx] * s;
    }
    __syncthreads();
    mbar_wait0(mbar);

    const int warp = tid >> 5, lane = tid & 31;

    // ================= Segment 1: 16r x 32v per warp (12 warps) =============
    // warp: rg = warp>>1 (rows 16rg..16rg+15), vh = warp&1
    // lane: lv = lane&7 (v0 = 32vh+4lv), lr = lane>>3; rows 16rg+lr+4rr
    {
        const int rg = warp >> 1, vh = warp & 1;
        const int lv = lane & 7, lr = lane >> 3;
        const int v0 = 32 * vh + 4 * lv;
        const ulonglong2* w1p = (const ulonglong2*)sw;
        const float* xb = sx0 + (16 * rg + lr) * T0W;

        u64 aA0 = 0, aB0 = 0, aA1 = 0, aB1 = 0;
        u64 aA2 = 0, aB2 = 0, aA3 = 0, aB3 = 0;

        #pragma unroll 4
        for (int k4 = 0; k4 < 16; k4++) {
            float4 x0 = *(const float4*)(xb + 4 * k4);
            float4 x1 = *(const float4*)(xb + 4 * T0W + 4 * k4);
            float4 x2 = *(const float4*)(xb + 8 * T0W + 4 * k4);
            float4 x3 = *(const float4*)(xb + 12 * T0W + 4 * k4);
            #pragma unroll
            for (int uu = 0; uu < 4; uu++) {
                ulonglong2 wp = w1p[(4 * k4 + uu) * 16 + 8 * vh + lv];
                float e0 = (uu == 0) ? x0.x : (uu == 1) ? x0.y : (uu == 2) ? x0.z : x0.w;
                float e1 = (uu == 0) ? x1.x : (uu == 1) ? x1.y : (uu == 2) ? x1.z : x1.w;
                float e2 = (uu == 0) ? x2.x : (uu == 1) ? x2.y : (uu == 2) ? x2.z : x2.w;
                float e3 = (uu == 0) ? x3.x : (uu == 1) ? x3.y : (uu == 2) ? x3.z : x3.w;
                u64 d0 = dup2(e0), d1 = dup2(e1), d2 = dup2(e2), d3 = dup2(e3);
                aA0 = fma2(d0, wp.x, aA0);  aB0 = fma2(d0, wp.y, aB0);
                aA1 = fma2(d1, wp.x, aA1);  aB1 = fma2(d1, wp.y, aB1);
                aA2 = fma2(d2, wp.x, aA2);  aB2 = fma2(d2, wp.y, aB2);
                aA3 = fma2(d3, wp.x, aA3);  aB3 = fma2(d3, wp.y, aB3);
            }
        }
        __syncthreads();   // all seg1 reads (cols 0-63) done everywhere
        float* pb = sx0 + (16 * rg + lr) * T0W + v0;
        {
            float4 o; unpack2(aA0, o.x, o.y); unpack2(aB0, o.z, o.w);
            *(float4*)(pb) = o;
        }
        {
            float4 o; unpack2(aA1, o.x, o.y); unpack2(aB1, o.z, o.w);
            *(float4*)(pb + 4 * T0W) = o;
        }
        {
            float4 o; unpack2(aA2, o.x, o.y); unpack2(aB2, o.z, o.w);
            *(float4*)(pb + 8 * T0W) = o;
        }
        {
            float4 o; unpack2(aA3, o.x, o.y); unpack2(aB3, o.z, o.w);
            *(float4*)(pb + 12 * T0W) = o;
        }
    }

    // ================= Segment 2: 4 rows/thread, v-pair =====================
    // ty = tid>>4 (0..23, rows ty+24s), tx = tid&15 (v-pair 2tx)
    {
        const int ty = tid >> 4, tx = tid & 15;
        const u64* w2p = (const u64*)(sw + 4096);
        u64 a2[4][3];
        #pragma unroll
        for (int s = 0; s < 4; s++)
            #pragma unroll
            for (int i = 0; i < 3; i++) a2[s][i] = 0ull;

        #pragma unroll
        for (int k4 = 0; k4 < 8; k4++) {        // k4 0-2: sx0 (cols 64-99); 3-7: sx1
            u64 wp0 = w2p[(4 * k4 + 0) * 16 + tx];
            u64 wp1 = w2p[(4 * k4 + 1) * 16 + tx];
            u64 wp2 = w2p[(4 * k4 + 2) * 16 + tx];
            u64 wp3 = w2p[(4 * k4 + 3) * 16 + tx];
            #pragma unroll
            for (int s = 0; s < 4; s++) {
                const int row = ty + 24 * s;
                const float* b = (k4 < 3) ? (sx0 + row * T0W + 64 + 12 * k4)
                                          : (sx1 + row * T1W + 12 * k4 - 36);
                float4 xb0 = *(const float4*)(b);
                float4 xb1 = *(const float4*)(b + 4);
                float4 xb2 = *(const float4*)(b + 8);
                a2[s][0] = fma2(dup2(xb0.x), wp0, a2[s][0]);
                a2[s][1] = fma2(dup2(xb0.y), wp0, a2[s][1]);
                a2[s][2] = fma2(dup2(xb0.z), wp0, a2[s][2]);
                a2[s][0] = fma2(dup2(xb0.w), wp1, a2[s][0]);
                a2[s][1] = fma2(dup2(xb1.x), wp1, a2[s][1]);
                a2[s][2] = fma2(dup2(xb1.y), wp1, a2[s][2]);
                a2[s][0] = fma2(dup2(xb1.z), wp2, a2[s][0]);
                a2[s][1] = fma2(dup2(xb1.w), wp2, a2[s][1]);
                a2[s][2] = fma2(dup2(xb2.x), wp2, a2[s][2]);
                a2[s][0] = fma2(dup2(xb2.y), wp3, a2[s][0]);
                a2[s][1] = fma2(dup2(xb2.z), wp3, a2[s][1]);
                a2[s][2] = fma2(dup2(xb2.w), wp3, a2[s][2]);
            }
        }
        __syncthreads();   // all seg2 reads (cols 64-159) done everywhere
        #pragma unroll
        for (int s = 0; s < 4; s++) {
            const int row = ty + 24 * s;
            float* p = (tx < 6) ? (sx0 + row * T0W + 64 + 6 * tx)
                                : (sx1 + row * T1W + 6 * tx - 36);
            float l0, h0, l1, h1, l2, h2;
            unpack2(a2[s][0], l0, h0);
            unpack2(a2[s][1], l1, h1);
            unpack2(a2[s][2], l2, h2);
            *(float2*)(p)     = make_float2(l0, l1);
            *(float2*)(p + 2) = make_float2(l2, h0);
            *(float2*)(p + 4) = make_float2(h1, h2);
        }
    }

    // ================= Segment 3: 8r x 16v per warp (12 warps) ==============
    // lane: lv3 = lane&7 (v-pair 2lv3), lr3 = lane>>3; rows 8warp+lr3, +4
    {
        const int lv3 = lane & 7, lr3 = lane >> 3;
        const int rbase = 8 * warp + lr3;          // rows rbase, rbase+4 (0..95)
        const u64* w3q = (const u64*)(sw + 5120);  // pair idx u*8+lv3
        u64 cA0 = 0, cA1 = 0, cA2 = 0, cA3 = 0, cA4 = 0;
        u64 cB0 = 0, cB1 = 0, cB2 = 0, cB3 = 0, cB4 = 0;

        #pragma unroll
        for (int k4 = 0; k4 < 4; k4++) {
            const float* pa = sx1 + rbase * T1W + 60 + 20 * k4;
            const float* pb = pa + 4 * T1W;
            float4 qa0 = *(const float4*)(pa);
            float4 qa1 = *(const float4*)(pa + 4);
            float4 qa2 = *(const float4*)(pa + 8);
            float4 qa3 = *(const float4*)(pa + 12);
            float4 qa4 = *(const float4*)(pa + 16);
            float4 qb0 = *(const float4*)(pb);
            float4 qb1 = *(const float4*)(pb + 4);
            float4 qb2 = *(const float4*)(pb + 8);
            float4 qb3 = *(const float4*)(pb + 12);
            float4 qb4 = *(const float4*)(pb + 16);
            u64 wu0 = w3q[(4 * k4 + 0) * 8 + lv3];
            u64 wu1 = w3q[(4 * k4 + 1) * 8 + lv3];
            u64 wu2 = w3q[(4 * k4 + 2) * 8 + lv3];
            u64 wu3 = w3q[(4 * k4 + 3) * 8 + lv3];
            cA0 = fma2(dup2(qa0.x), wu0, cA0);  cB0 = fma2(dup2(qb0.x), wu0, cB0);
            cA1 = fma2(dup2(qa0.y), wu0, cA1);  cB1 = fma2(dup2(qb0.y), wu0, cB1);
            cA2 = fma2(dup2(qa0.z), wu0, cA2);  cB2 = fma2(dup2(qb0.z), wu0, cB2);
            cA3 = fma2(dup2(qa0.w), wu0, cA3);  cB3 = fma2(dup2(qb0.w), wu0, cB3);
            cA4 = fma2(dup2(qa1.x), wu0, cA4);  cB4 = fma2(dup2(qb1.x), wu0, cB4);
            cA0 = fma2(dup2(qa1.y), wu1, cA0);  cB0 = fma2(dup2(qb1.y), wu1, cB0);
            cA1 = fma2(dup2(qa1.z), wu1, cA1);  cB1 = fma2(dup2(qb1.z), wu1, cB1);
            cA2 = fma2(dup2(qa1.w), wu1, cA2);  cB2 = fma2(dup2(qb1.w), wu1, cB2);
            cA3 = fma2(dup2(qa2.x), wu1, cA3);  cB3 = fma2(dup2(qb2.x), wu1, cB3);
            cA4 = fma2(dup2(qa2.y), wu1, cA4);  cB4 = fma2(dup2(qb2.y), wu1, cB4);
            cA0 = fma2(dup2(qa2.z), wu2, cA0);  cB0 = fma2(dup2(qb2.z), wu2, cB0);
            cA1 = fma2(dup2(qa2.w), wu2, cA1);  cB1 = fma2(dup2(qb2.w), wu2, cB1);
            cA2 = fma2(dup2(qa3.x), wu2, cA2);  cB2 = fma2(dup2(qb3.x), wu2, cB2);
            cA3 = fma2(dup2(qa3.y), wu2, cA3);  cB3 = fma2(dup2(qb3.y), wu2, cB3);
            cA4 = fma2(dup2(qa3.z), wu2, cA4);  cB4 = fma2(dup2(qb3.z), wu2, cB4);
            cA0 = fma2(dup2(qa3.w), wu3, cA0);  cB0 = fma2(dup2(qb3.w), wu3, cB0);
            cA1 = fma2(dup2(qa4.x), wu3, cA1);  cB1 = fma2(dup2(qb4.x), wu3, cB1);
            cA2 = fma2(dup2(qa4.y), wu3, cA2);  cB2 = fma2(dup2(qb4.y), wu3, cB2);
            cA3 = fma2(dup2(qa4.z), wu3, cA3);  cB3 = fma2(dup2(qb4.z), wu3, cB3);
            cA4 = fma2(dup2(qa4.w), wu3, cA4);  cB4 = fma2(dup2(qb4.w), wu3, cB4);
        }
        __syncthreads();   // all seg3 reads done everywhere
        float* pA = sx1 + rbase * T1W + 60 + 10 * lv3;
        float* pB = pA + 4 * T1W;
        float l0, h0, l1, h1, l2, h2, l3, h3, l4, h4;
        unpack2(cA0, l0, h0); unpack2(cA1, l1, h1); unpack2(cA2, l2, h2);
        unpack2(cA3, l3, h3); unpack2(cA4, l4, h4);
        *(float2*)(pA)     = make_float2(l0, l1);
        *(float2*)(pA + 2) = make_float2(l2, l3);
        *(float2*)(pA + 4) = make_float2(l4, h0);
        *(float2*)(pA + 6) = make_float2(h1, h2);
        *(float2*)(pA + 8) = make_float2(h3, h4);
        unpack2(cB0, l0, h0); unpack2(cB1, l1, h1); unpack2(cB2, l2, h2);
        unpack2(cB3, l3, h3); unpack2(cB4, l4, h4);
        *(float2*)(pB)     = make_float2(l0, l1);
        *(float2*)(pB + 2) = make_float2(l2, l3);
        *(float2*)(pB + 4) = make_float2(l4, h0);
        *(float2*)(pB + 6) = make_float2(h1, h2);
        *(float2*)(pB + 8) = make_float2(h3, h4);
    }

    __syncthreads();
    if (tid == 0) {
        asm volatile("fence.proxy.async;" ::: "memory");
        tma_store2d(&mo0, 0,   row0, s2u(sx0));   // TMA clips OOB rows
        tma_store2d(&mo1, 100, row0, s2u(sx1));
        asm volatile("cp.async.bulk.commit_group;" ::: "memory");
        asm volatile("cp.async.bulk.wait_group 0;" ::: "memory");
    }
}

// ===================== host side =====================

typedef CUresult (*TmapEncodeFn)(
    CUtensorMap*, CUtensorMapDataType, cuuint32_t, void*,
    const cuuint64_t*, const cuuint64_t*, const cuuint32_t*, const cuuint32_t*,
    CUtensorMapInterleave, CUtensorMapSwizzle, CUtensorMapL2promotion,
    CUtensorMapFloatOOBfill);

static void enc_map(TmapEncodeFn f, CUtensorMap* m, void* base, long long n,
                    uint32_t boxw) {
    cuuint64_t dims[2]    = {240, (cuuint64_t)n};
    cuuint64_t strides[1] = {240 * 4};
    cuuint32_t box[2]     = {boxw, TROWS};
    cuuint32_t es[2]      = {1, 1};
    f(m, CU_TENSOR_MAP_DATA_TYPE_FLOAT32, 2, base, dims, strides, box, es,
      CU_TENSOR_MAP_INTERLEAVE_NONE, CU_TENSOR_MAP_SWIZZLE_NONE,
      CU_TENSOR_MAP_L2_PROMOTION_L2_128B, CU_TENSOR_MAP_FLOAT_OOB_FILL_NONE);
}

extern "C" void kernel_launch(void* const* d_in, const int* in_sizes, int n_in,
                              void* d_out, int out_size) {
    void* x = d_in[0];
    const float* w = (const float*)d_in[1];
    const long long n = in_sizes[0] / 240;               // 200000
    const int blocks = (int)((n + TROWS - 1) / TROWS);   // 2084

    void* fp = nullptr;
    cudaDriverEntryPointQueryResult qr;
#if CUDART_VERSION >= 12050
    cudaGetDriverEntryPointByVersion("cuTensorMapEncodeTiled", &fp, 12000,
                                     cudaEnableDefault, &qr);
#else
    cudaGetDriverEntryPoint("cuTensorMapEncodeTiled", &fp, cudaEnableDefault, &qr);
#endif
    TmapEncodeFn enc = (TmapEncodeFn)fp;

    CUtensorMap mi0, mi1, mo0, mo1;
    enc_map(enc, &mi0, x, n, 100);
    enc_map(enc, &mi1, x, n, 140);
    enc_map(enc, &mo0, d_out, n, 100);
    enc_map(enc, &mo1, d_out, n, 140);

    static bool attr_set = false;
    if (!attr_set) {
        cudaFuncSetAttribute(eqlin_kernel,
                             cudaFuncAttributeMaxDynamicSharedMemorySize, SMEM_BYTES);
        attr_set = true;
    }
    eqlin_kernel<<<blocks, NTHR, SMEM_BYTES>>>(mi0, mi1, mo0, mo1, w);
}

// round 17
// speedup vs baseline: 1.4502x; 1.1213x over previous
#include <cuda.h>
#include <cuda_runtime.h>
#include <cstdint>

// Equivariant linear: segments (u,i) = (64,1),(32,3),(16,5); in==out dim 240.
// Barrier-free warp specialization: warps 0-5 do seg1 (16r x 64v self-contained
// tiles), warps 6-11 do seg2+seg3 (intra-warp row sharing only). Only syncs:
// post-staging and pre-TMA-store. 96-row tiles, 384 threads, 2 CTAs/SM.

typedef unsigned long long u64;

__device__ __forceinline__ u64 fma2(u64 a, u64 b, u64 c) {
    u64 d;
    asm("fma.rn.f32x2 %0, %1, %2, %3;" : "=l"(d) : "l"(a), "l"(b), "l"(c));
    return d;
}
__device__ __forceinline__ u64 dup2(float x) {
    u64 d;
    asm("mov.b64 %0, {%1, %2};" : "=l"(d) : "f"(x), "f"(x));
    return d;
}
__device__ __forceinline__ void unpack2(u64 v, float& a, float& b) {
    asm("mov.b64 {%0, %1}, %2;" : "=f"(a), "=f"(b) : "l"(v));
}
__device__ __forceinline__ uint32_t s2u(const void* p) {
    uint32_t a;
    asm("{ .reg .u64 t; cvta.to.shared.u64 t, %1; cvt.u32.u64 %0, t; }"
        : "=r"(a) : "l"(p));
    return a;
}
__device__ __forceinline__ void mbar_wait0(uint32_t mbar) {
    asm volatile(
        "{\n\t.reg .pred P;\n\t"
        "W%=:\n\t"
        "mbarrier.try_wait.parity.shared.b64 P, [%0], 0;\n\t"
        "@P bra.uni D%=;\n\t"
        "bra.uni W%=;\n\t"
        "D%=:\n\t}"
        :: "r"(mbar) : "memory");
}
__device__ __forceinline__ void tma_load2d(uint32_t dst, const CUtensorMap* m,
                                           int cx, int cy, uint32_t mbar) {
    asm volatile(
        "cp.async.bulk.tensor.2d.shared::cta.global.tile.mbarrier::complete_tx::bytes "
        "[%0], [%1, {%2, %3}], [%4];"
        :: "r"(dst), "l"(m), "r"(cx), "r"(cy), "r"(mbar) : "memory");
}
__device__ __forceinline__ void tma_store2d(const CUtensorMap* m, int cx, int cy,
                                            uint32_t src) {
    asm volatile(
        "cp.async.bulk.tensor.2d.global.shared::cta.tile.bulk_group "
        "[%0, {%1, %2}], [%3];"
        :: "l"(m), "r"(cx), "r"(cy), "r"(src) : "memory");
}

#define T0W 100
#define T1W 140
#define TROWS 96
#define NTHR 384
#define SX0_OFF 5376
#define SX1_OFF (SX0_OFF + TROWS * T0W)      // 14976
#define MBAR_OFF (SX1_OFF + TROWS * T1W)     // 28416
#define SMEM_BYTES ((MBAR_OFF + 4) * 4)      // 113680

__global__ __launch_bounds__(NTHR, 2) void eqlin_kernel(
    const __grid_constant__ CUtensorMap mi0,
    const __grid_constant__ CUtensorMap mi1,
    const __grid_constant__ CUtensorMap mo0,
    const __grid_constant__ CUtensorMap mo1,
    const float* __restrict__ w)
{
    extern __shared__ __align__(128) float sm[];
    float* sw  = sm;
    float* sx0 = sm + SX0_OFF;
    float* sx1 = sm + SX1_OFF;
    const uint32_t mbar = s2u(sm + MBAR_OFF);

    const int tid = threadIdx.x;
    const int row0 = blockIdx.x * TROWS;

    if (tid == 0)
        asm volatile("mbarrier.init.shared.b64 [%0], 1;" :: "r"(mbar) : "memory");
    __syncthreads();
    if (tid == 0) {
        // OOB rows zero-fill on load, clip on store: no predicates needed.
        asm volatile("mbarrier.arrive.expect_tx.shared.b64 _, [%0], 92160;"
                     :: "r"(mbar) : "memory");
        tma_load2d(s2u(sx0), &mi0, 0,   row0, mbar);
        tma_load2d(s2u(sx1), &mi1, 100, row0, mbar);
    }

    // ---- stage weights (overlaps TMA), pre-scaled, plain layout ----
    #pragma unroll
    for (int k = 0; k < 14; k++) {               // 14*384 = 5376 exactly
        int idx = tid + k * NTHR;
        float s = (idx < 4096) ? 0.125f
                 : (idx < 5120) ? 0.17677669529663687f
                                : 0.25f;
        sw[idx] = w[idx] * s;
    }
    __syncthreads();   // staging visible to all (only intermediate barrier)
    mbar_wait0(mbar);

    const int warp = tid >> 5, lane = tid & 31;

    if (warp < 6) {
        // ============ Warps 0-5: Segment 1, warp tile 16r x 64v ============
        // lane: lv = lane&15 (v0 = 4lv), lr = lane>>4; rows 16w + lr + 2rr
        const int lv = lane & 15, lr = lane >> 4;
        const int rbase = 16 * warp + lr;
        const ulonglong2* w1p = (const ulonglong2*)sw;   // idx u*16 + lv
        const float* xb = sx0 + rbase * T0W;

        u64 aA0 = 0, aB0 = 0, aA1 = 0, aB1 = 0;
        u64 aA2 = 0, aB2 = 0, aA3 = 0, aB3 = 0;
        u64 aA4 = 0, aB4 = 0, aA5 = 0, aB5 = 0;
        u64 aA6 = 0, aB6 = 0, aA7 = 0, aB7 = 0;

        #pragma unroll 1
        for (int k4 = 0; k4 < 16; k4++) {
            float4 x0 = *(const float4*)(xb + 0  * T0W + 4 * k4);
            float4 x1 = *(const float4*)(xb + 2  * T0W + 4 * k4);
            float4 x2 = *(const float4*)(xb + 4  * T0W + 4 * k4);
            float4 x3 = *(const float4*)(xb + 6  * T0W + 4 * k4);
            float4 x4 = *(const float4*)(xb + 8  * T0W + 4 * k4);
            float4 x5 = *(const float4*)(xb + 10 * T0W + 4 * k4);
            float4 x6 = *(const float4*)(xb + 12 * T0W + 4 * k4);
            float4 x7 = *(const float4*)(xb + 14 * T0W + 4 * k4);
            #pragma unroll
            for (int uu = 0; uu < 4; uu++) {
                ulonglong2 wp = w1p[(4 * k4 + uu) * 16 + lv];
                float e0 = (uu == 0) ? x0.x : (uu == 1) ? x0.y : (uu == 2) ? x0.z : x0.w;
                float e1 = (uu == 0) ? x1.x : (uu == 1) ? x1.y : (uu == 2) ? x1.z : x1.w;
                float e2 = (uu == 0) ? x2.x : (uu == 1) ? x2.y : (uu == 2) ? x2.z : x2.w;
                float e3 = (uu == 0) ? x3.x : (uu == 1) ? x3.y : (uu == 2) ? x3.z : x3.w;
                float e4 = (uu == 0) ? x4.x : (uu == 1) ? x4.y : (uu == 2) ? x4.z : x4.w;
                float e5 = (uu == 0) ? x5.x : (uu == 1) ? x5.y : (uu == 2) ? x5.z : x5.w;
                float e6 = (uu == 0) ? x6.x : (uu == 1) ? x6.y : (uu == 2) ? x6.z : x6.w;
                float e7 = (uu == 0) ? x7.x : (uu == 1) ? x7.y : (uu == 2) ? x7.z : x7.w;
                u64 d;
                d = dup2(e0); aA0 = fma2(d, wp.x, aA0); aB0 = fma2(d, wp.y, aB0);
                d = dup2(e1); aA1 = fma2(d, wp.x, aA1); aB1 = fma2(d, wp.y, aB1);
                d = dup2(e2); aA2 = fma2(d, wp.x, aA2); aB2 = fma2(d, wp.y, aB2);
                d = dup2(e3); aA3 = fma2(d, wp.x, aA3); aB3 = fma2(d, wp.y, aB3);
                d = dup2(e4); aA4 = fma2(d, wp.x, aA4); aB4 = fma2(d, wp.y, aB4);
                d = dup2(e5); aA5 = fma2(d, wp.x, aA5); aB5 = fma2(d, wp.y, aB5);
                d = dup2(e6); aA6 = fma2(d, wp.x, aA6); aB6 = fma2(d, wp.y, aB6);
                d = dup2(e7); aA7 = fma2(d, wp.x, aA7); aB7 = fma2(d, wp.y, aB7);
            }
        }
        // Self-contained warp tile: program order makes stores safe (no barrier)
        float* pb = sx0 + rbase * T0W + 4 * lv;
        {
            float4 o; unpack2(aA0, o.x, o.y); unpack2(aB0, o.z, o.w);
            *(float4*)(pb + 0 * T0W) = o;
        }
        {
            float4 o; unpack2(aA1, o.x, o.y); unpack2(aB1, o.z, o.w);
            *(float4*)(pb + 2 * T0W) = o;
        }
        {
            float4 o; unpack2(aA2, o.x, o.y); unpack2(aB2, o.z, o.w);
            *(float4*)(pb + 4 * T0W) = o;
        }
        {
            float4 o; unpack2(aA3, o.x, o.y); unpack2(aB3, o.z, o.w);
            *(float4*)(pb + 6 * T0W) = o;
        }
        {
            float4 o; unpack2(aA4, o.x, o.y); unpack2(aB4, o.z, o.w);
            *(float4*)(pb + 8 * T0W) = o;
        }
        {
            float4 o; unpack2(aA5, o.x, o.y); unpack2(aB5, o.z, o.w);
            *(float4*)(pb + 10 * T0W) = o;
        }
        {
            float4 o; unpack2(aA6, o.x, o.y); unpack2(aB6, o.z, o.w);
            *(float4*)(pb + 12 * T0W) = o;
        }
        {
            float4 o; unpack2(aA7, o.x, o.y); unpack2(aB7, o.z, o.w);
            *(float4*)(pb + 14 * T0W) = o;
        }
    } else {
        // ============ Warps 6-11: Segment 2 then Segment 3 ============
        const int t2 = tid - 192;
        const int tx2 = t2 & 7;            // v0 = 4*tx2 (v-quad)
        const int ty2 = t2 >> 3;           // 0..23
        const ulonglong2* w2q = (const ulonglong2*)(sw + 4096);  // idx u*8+tx2

        // ---- seg2: 2 passes x 2 rows (rows ty2+24s; pass p: s = 2p, 2p+1)
        #pragma unroll
        for (int p = 0; p < 2; p++) {
            const int rA = ty2 + 48 * p;
            const int rB = rA + 24;
            u64 aA0 = 0, aA1 = 0, aA2 = 0, aC0 = 0, aC1 = 0, aC2 = 0;  // row rA
            u64 bA0 = 0, bA1 = 0, bA2 = 0, bC0 = 0, bC1 = 0, bC2 = 0;  // row rB
            #pragma unroll
            for (int k4 = 0; k4 < 8; k4++) {
                ulonglong2 w0 = w2q[(4 * k4 + 0) * 8 + tx2];
                ulonglong2 w1 = w2q[(4 * k4 + 1) * 8 + tx2];
                ulonglong2 w2 = w2q[(4 * k4 + 2) * 8 + tx2];
                ulonglong2 w3 = w2q[(4 * k4 + 3) * 8 + tx2];
                const float* ba = (k4 < 3) ? (sx0 + rA * T0W + 64 + 12 * k4)
                                           : (sx1 + rA * T1W + 12 * k4 - 36);
                const float* bb = (k4 < 3) ? (sx0 + rB * T0W + 64 + 12 * k4)
                                           : (sx1 + rB * T1W + 12 * k4 - 36);
                float4 qa0 = *(const float4*)(ba);
                float4 qa1 = *(const float4*)(ba + 4);
                float4 qa2 = *(const float4*)(ba + 8);
                float4 qb0 = *(const float4*)(bb);
                float4 qb1 = *(const float4*)(bb + 4);
                float4 qb2 = *(const float4*)(bb + 8);
                u64 d;
                // row rA
                d = dup2(qa0.x); aA0 = fma2(d, w0.x, aA0); aC0 = fma2(d, w0.y, aC0);
                d = dup2(qa0.y); aA1 = fma2(d, w0.x, aA1); aC1 = fma2(d, w0.y, aC1);
                d = dup2(qa0.z); aA2 = fma2(d, w0.x, aA2); aC2 = fma2(d, w0.y, aC2);
                d = dup2(qa0.w); aA0 = fma2(d, w1.x, aA0); aC0 = fma2(d, w1.y, aC0);
                d = dup2(qa1.x); aA1 = fma2(d, w1.x, aA1); aC1 = fma2(d, w1.y, aC1);
                d = dup2(qa1.y); aA2 = fma2(d, w1.x, aA2); aC2 = fma2(d, w1.y, aC2);
                d = dup2(qa1.z); aA0 = fma2(d, w2.x, aA0); aC0 = fma2(d, w2.y, aC0);
                d = dup2(qa1.w); aA1 = fma2(d, w2.x, aA1); aC1 = fma2(d, w2.y, aC1);
                d = dup2(qa2.x); aA2 = fma2(d, w2.x, aA2); aC2 = fma2(d, w2.y, aC2);
                d = dup2(qa2.y); aA0 = fma2(d, w3.x, aA0); aC0 = fma2(d, w3.y, aC0);
                d = dup2(qa2.z); aA1 = fma2(d, w3.x, aA1); aC1 = fma2(d, w3.y, aC1);
                d = dup2(qa2.w); aA2 = fma2(d, w3.x, aA2); aC2 = fma2(d, w3.y, aC2);
                // row rB
                d = dup2(qb0.x); bA0 = fma2(d, w0.x, bA0); bC0 = fma2(d, w0.y, bC0);
                d = dup2(qb0.y); bA1 = fma2(d, w0.x, bA1); bC1 = fma2(d, w0.y, bC1);
                d = dup2(qb0.z); bA2 = fma2(d, w0.x, bA2); bC2 = fma2(d, w0.y, bC2);
                d = dup2(qb0.w); bA0 = fma2(d, w1.x, bA0); bC0 = fma2(d, w1.y, bC0);
                d = dup2(qb1.x); bA1 = fma2(d, w1.x, bA1); bC1 = fma2(d, w1.y, bC1);
                d = dup2(qb1.y); bA2 = fma2(d, w1.x, bA2); bC2 = fma2(d, w1.y, bC2);
                d = dup2(qb1.z); bA0 = fma2(d, w2.x, bA0); bC0 = fma2(d, w2.y, bC0);
                d = dup2(qb1.w); bA1 = fma2(d, w2.x, bA1); bC1 = fma2(d, w2.y, bC1);
                d = dup2(qb2.x); bA2 = fma2(d, w2.x, bA2); bC2 = fma2(d, w2.y, bC2);
                d = dup2(qb2.y); bA0 = fma2(d, w3.x, bA0); bC0 = fma2(d, w3.y, bC0);
                d = dup2(qb2.z); bA1 = fma2(d, w3.x, bA1); bC1 = fma2(d, w3.y, bC1);
                d = dup2(qb2.w); bA2 = fma2(d, w3.x, bA2); bC2 = fma2(d, w3.y, bC2);
            }
            // store rows rA, rB: 12 contiguous cols at 64 + 12*tx2
            // pass-1 writes rows 0..47 only; pass-2 reads rows 48..95: disjoint.
            {
                float* pd = (tx2 < 3) ? (sx0 + rA * T0W + 64 + 12 * tx2)
                                      : (sx1 + rA * T1W + 12 * tx2 - 36);
                float l0, h0, l1, h1, l2, h2, m0, n0, m1, n1, m2, n2;
                unpack2(aA0, l0, h0); unpack2(aA1, l1, h1); unpack2(aA2, l2, h2);
                unpack2(aC0, m0, n0); unpack2(aC1, m1, n1); unpack2(aC2, m2, n2);
                *(float4*)(pd)     = make_float4(l0, l1, l2, h0);
                *(float4*)(pd + 4) = make_float4(h1, h2, m0, m1);
                *(float4*)(pd + 8) = make_float4(m2, n0, n1, n2);
            }
            {
                float* pd = (tx2 < 3) ? (sx0 + rB * T0W + 64 + 12 * tx2)
                                      : (sx1 + rB * T1W + 12 * tx2 - 36);
                float l0, h0, l1, h1, l2, h2, m0, n0, m1, n1, m2, n2;
                unpack2(bA0, l0, h0); unpack2(bA1, l1, h1); unpack2(bA2, l2, h2);
                unpack2(bC0, m0, n0); unpack2(bC1, m1, n1); unpack2(bC2, m2, n2);
                *(float4*)(pd)     = make_float4(l0, l1, l2, h0);
                *(float4*)(pd + 4) = make_float4(h1, h2, m0, m1);
                *(float4*)(pd + 8) = make_float4(m2, n0, n1, n2);
            }
        }

        // ---- seg3: 2 passes x 2 rows; warp w3 owns rows 16w3..16w3+15
        const int w3 = warp - 6;
        const int lv3 = lane & 7, lr3 = lane >> 3;
        const u64* w3q = (const u64*)(sw + 5120);  // pair idx u*8+lv3
        #pragma unroll
        for (int pp = 0; pp < 2; pp++) {
            const int rbase = 16 * w3 + lr3 + 8 * pp;   // rows rbase, rbase+4
            u64 cA0 = 0, cA1 = 0, cA2 = 0, cA3 = 0, cA4 = 0;
            u64 cB0 = 0, cB1 = 0, cB2 = 0, cB3 = 0, cB4 = 0;
            #pragma unroll
            for (int k4 = 0; k4 < 4; k4++) {
                const float* pa = sx1 + rbase * T1W + 60 + 20 * k4;
                const float* pb = pa + 4 * T1W;
                float4 qa0 = *(const float4*)(pa);
                float4 qa1 = *(const float4*)(pa + 4);
                float4 qa2 = *(const float4*)(pa + 8);
                float4 qa3 = *(const float4*)(pa + 12);
                float4 qa4 = *(const float4*)(pa + 16);
                float4 qb0 = *(const float4*)(pb);
                float4 qb1 = *(const float4*)(pb + 4);
                float4 qb2 = *(const float4*)(pb + 8);
                float4 qb3 = *(const float4*)(pb + 12);
                float4 qb4 = *(const float4*)(pb + 16);
                u64 wu0 = w3q[(4 * k4 + 0) * 8 + lv3];
                u64 wu1 = w3q[(4 * k4 + 1) * 8 + lv3];
                u64 wu2 = w3q[(4 * k4 + 2) * 8 + lv3];
                u64 wu3 = w3q[(4 * k4 + 3) * 8 + lv3];
                cA0 = fma2(dup2(qa0.x), wu0, cA0);  cB0 = fma2(dup2(qb0.x), wu0, cB0);
                cA1 = fma2(dup2(qa0.y), wu0, cA1);  cB1 = fma2(dup2(qb0.y), wu0, cB1);
                cA2 = fma2(dup2(qa0.z), wu0, cA2);  cB2 = fma2(dup2(qb0.z), wu0, cB2);
                cA3 = fma2(dup2(qa0.w), wu0, cA3);  cB3 = fma2(dup2(qb0.w), wu0, cB3);
                cA4 = fma2(dup2(qa1.x), wu0, cA4);  cB4 = fma2(dup2(qb1.x), wu0, cB4);
                cA0 = fma2(dup2(qa1.y), wu1, cA0);  cB0 = fma2(dup2(qb1.y), wu1, cB0);
                cA1 = fma2(dup2(qa1.z), wu1, cA1);  cB1 = fma2(dup2(qb1.z), wu1, cB1);
                cA2 = fma2(dup2(qa1.w), wu1, cA2);  cB2 = fma2(dup2(qb1.w), wu1, cB2);
                cA3 = fma2(dup2(qa2.x), wu1, cA3);  cB3 = fma2(dup2(qb2.x), wu1, cB3);
                cA4 = fma2(dup2(qa2.y), wu1, cA4);  cB4 = fma2(dup2(qb2.y), wu1, cB4);
                cA0 = fma2(dup2(qa2.z), wu2, cA0);  cB0 = fma2(dup2(qb2.z), wu2, cB0);
                cA1 = fma2(dup2(qa2.w), wu2, cA1);  cB1 = fma2(dup2(qb2.w), wu2, cB1);
                cA2 = fma2(dup2(qa3.x), wu2, cA2);  cB2 = fma2(dup2(qb3.x), wu2, cB2);
                cA3 = fma2(dup2(qa3.y), wu2, cA3);  cB3 = fma2(dup2(qb3.y), wu2, cB3);
                cA4 = fma2(dup2(qa3.z), wu2, cA4);  cB4 = fma2(dup2(qb3.z), wu2, cB4);
                cA0 = fma2(dup2(qa3.w), wu3, cA0);  cB0 = fma2(dup2(qb3.w), wu3, cB0);
                cA1 = fma2(dup2(qa4.x), wu3, cA1);  cB1 = fma2(dup2(qb4.x), wu3, cB1);
                cA2 = fma2(dup2(qa4.y), wu3, cA2);  cB2 = fma2(dup2(qb4.y), wu3, cB2);
                cA3 = fma2(dup2(qa4.z), wu3, cA3);  cB3 = fma2(dup2(qb4.z), wu3, cB3);
                cA4 = fma2(dup2(qa4.w), wu3, cA4);  cB4 = fma2(dup2(qb4.w), wu3, cB4);
            }
            float* pA = sx1 + rbase * T1W + 60 + 10 * lv3;
            float* pB = pA + 4 * T1W;
            float l0, h0, l1, h1, l2, h2, l3, h3, l4, h4;
            unpack2(cA0, l0, h0); unpack2(cA1, l1, h1); unpack2(cA2, l2, h2);
            unpack2(cA3, l3, h3); unpack2(cA4, l4, h4);
            *(float2*)(pA)     = make_float2(l0, l1);
            *(float2*)(pA + 2) = make_float2(l2, l3);
            *(float2*)(pA + 4) = make_float2(l4, h0);
            *(float2*)(pA + 6) = make_float2(h1, h2);
            *(float2*)(pA + 8) = make_float2(h3, h4);
            unpack2(cB0, l0, h0); unpack2(cB1, l1, h1); unpack2(cB2, l2, h2);
            unpack2(cB3, l3, h3); unpack2(cB4, l4, h4);
            *(float2*)(pB)     = make_float2(l0, l1);
            *(float2*)(pB + 2) = make_float2(l2, l3);
            *(float2*)(pB + 4) = make_float2(l4, h0);
            *(float2*)(pB + 6) = make_float2(h1, h2);
            *(float2*)(pB + 8) = make_float2(h3, h4);
        }
    }

    __syncthreads();   // all outputs in smem
    if (tid == 0) {
        asm volatile("fence.proxy.async;" ::: "memory");
        tma_store2d(&mo0, 0,   row0, s2u(sx0));   // TMA clips OOB rows
        tma_store2d(&mo1, 100, row0, s2u(sx1));
        asm volatile("cp.async.bulk.commit_group;" ::: "memory");
        asm volatile("cp.async.bulk.wait_group 0;" ::: "memory");
    }
}

// ===================== host side =====================

typedef CUresult (*TmapEncodeFn)(
    CUtensorMap*, CUtensorMapDataType, cuuint32_t, void*,
    const cuuint64_t*, const cuuint64_t*, const cuuint32_t*, const cuuint32_t*,
    CUtensorMapInterleave, CUtensorMapSwizzle, CUtensorMapL2promotion,
    CUtensorMapFloatOOBfill);

static void enc_map(TmapEncodeFn f, CUtensorMap* m, void* base, long long n,
                    uint32_t boxw) {
    cuuint64_t dims[2]    = {240, (cuuint64_t)n};
    cuuint64_t strides[1] = {240 * 4};
    cuuint32_t box[2]     = {boxw, TROWS};
    cuuint32_t es[2]      = {1, 1};
    f(m, CU_TENSOR_MAP_DATA_TYPE_FLOAT32, 2, base, dims, strides, box, es,
      CU_TENSOR_MAP_INTERLEAVE_NONE, CU_TENSOR_MAP_SWIZZLE_NONE,
      CU_TENSOR_MAP_L2_PROMOTION_L2_128B, CU_TENSOR_MAP_FLOAT_OOB_FILL_NONE);
}

extern "C" void kernel_launch(void* const* d_in, const int* in_sizes, int n_in,
                              void* d_out, int out_size) {
    void* x = d_in[0];
    const float* w = (const float*)d_in[1];
    const long long n = in_sizes[0] / 240;               // 200000
    const int blocks = (int)((n + TROWS - 1) / TROWS);   // 2084

    void* fp = nullptr;
    cudaDriverEntryPointQueryResult qr;
#if CUDART_VERSION >= 12050
    cudaGetDriverEntryPointByVersion("cuTensorMapEncodeTiled", &fp, 12000,
                                     cudaEnableDefault, &qr);
#else
    cudaGetDriverEntryPoint("cuTensorMapEncodeTiled", &fp, cudaEnableDefault, &qr);
#endif
    TmapEncodeFn enc = (TmapEncodeFn)fp;

    CUtensorMap mi0, mi1, mo0, mo1;
    enc_map(enc, &mi0, x, n, 100);
    enc_map(enc, &mi1, x, n, 140);
    enc_map(enc, &mo0, d_out, n, 100);
    enc_map(enc, &mo1, d_out, n, 140);

    static bool attr_set = false;
    if (!attr_set) {
        cudaFuncSetAttribute(eqlin_kernel,
                             cudaFuncAttributeMaxDynamicSharedMemorySize, SMEM_BYTES);
        attr_set = true;
    }
    eqlin_kernel<<<blocks, NTHR, SMEM_BYTES>>>(mi0, mi1, mo0, mo1, w);
}